// round 8
// baseline (speedup 1.0000x reference)
#include <cuda_runtime.h>
#include <float.h>

// Fused MaxPool(2x2,s1,SAME) -> depthwise 3x3 binomial blur -> AvgPool(2x2,s2)
// == separable 4x4 stencil w=(1,3,3,1)/8 stride 2 over maxpool output y.
//
// R8: R3's exact pipeline shape (double-buffered column pairs, 14-load
// 256B-wide bursts, full compute block between burst and consume) with the
// register-dieted boundary scheme (clamped uniform offsets) and a 104-reg
// cap -> 5 CTAs/SM = 20 warps. Streaming stores keep L2 for input reuse.

#define NROWP  28
#define ROWSTR (112*64)     // float2 per x row
#define PXSTR  64           // float2 per pixel

__device__ __forceinline__ float2 f2max(float2 a, float2 b) {
    return make_float2(fmaxf(a.x,b.x), fmaxf(a.y,b.y));
}
__device__ __forceinline__ void f2fma(float2& a, float w, float2 v) {
    a.x = fmaf(w, v.x, a.x); a.y = fmaf(w, v.y, a.y);
}

// Load 7 clamped rows of column xc0+T. Addresses always in-bounds;
// out-of-range VALUES are neutralized at consume time (MAKECM / STEP).
#define LOADCOL(dst, T) do {                                              \
    int _cc = xc0 + (T);                                                  \
    _cc = _cc < 0 ? 0 : (_cc > 111 ? 111 : _cc);                          \
    const float2* _p = base + (size_t)_cc * PXSTR;                        \
    dst[0] = __ldg(_p + rowOff[0]);                                       \
    dst[1] = __ldg(_p + rowOff[1]);                                       \
    dst[2] = __ldg(_p + rowOff[2]);                                       \
    dst[3] = __ldg(_p + rowOff[3]);                                       \
    dst[4] = __ldg(_p + rowOff[4]);                                       \
    dst[5] = __ldg(_p + rowOff[5]);                                       \
    dst[6] = __ldg(_p + rowOff[6]);                                       \
} while (0)

// Column pair-maxes; bottom strip's x row 112 (xv[5]) is -inf SAME padding.
#define MAKECM(cm, xv) do {                                               \
    const float2 _x5 = okBot ? xv[5] : NEG;                               \
    cm[0] = f2max(xv[0], xv[1]);                                          \
    cm[1] = f2max(xv[1], xv[2]);                                          \
    cm[2] = f2max(xv[2], xv[3]);                                          \
    cm[3] = f2max(xv[3], xv[4]);                                          \
    cm[4] = f2max(xv[4], _x5);                                            \
    cm[5] = f2max(_x5,   xv[6]);                                          \
} while (0)

// Finalize y column ty (literal after unroll): vertical (1,3,3,1)/8 then
// scatter into the 2-slot per-row accumulator ring.
#define STEP(prevcm, curcm, TY) do {                                      \
    const bool _skip = ((TY)==0 && leftSkip) || ((TY)==29 && rightSkip);  \
    if (!_skip) {                                                         \
        float2 yc[6];                                                     \
        _Pragma("unroll")                                                 \
        for (int _k = 0; _k < 6; _k++)                                    \
            yc[_k] = f2max(prevcm[_k], curcm[_k]);                        \
        if (!okTop) yc[0] = ZERO;                                         \
        if (!okBot) yc[5] = ZERO;                                         \
        const int   _m  = (TY) >> 1;                                      \
        const float _wA = ((TY) & 1) ? wv1 : wv0;                         \
        const float _wB = ((TY) & 1) ? wv0 : wv1;                         \
        _Pragma("unroll")                                                 \
        for (int _rl = 0; _rl < 2; _rl++) {                               \
            float2 V = ZERO;                                              \
            f2fma(V, wv0, yc[2*_rl + 0]);                                 \
            f2fma(V, wv1, yc[2*_rl + 1]);                                 \
            f2fma(V, wv1, yc[2*_rl + 2]);                                 \
            f2fma(V, wv0, yc[2*_rl + 3]);                                 \
            if (_m < 14) f2fma(acc[_rl][_m & 1], _wA, V);                 \
            if (_m >= 1) f2fma(acc[_rl][(_m & 1) ^ 1], _wB, V);           \
        }                                                                 \
    }                                                                     \
} while (0)

__global__ void __launch_bounds__(128, 5)
mbp_kernel(const float2* __restrict__ x, float2* __restrict__ out) {
    const int lane   = threadIdx.x;
    const int wid    = blockIdx.x * 4 + threadIdx.y;   // 7168 warp tasks
    const int chHalf = wid & 1;
    const int strip  = wid >> 1;                       // 3584 strips
    const int cj = strip & 3;                          // 4 col chunks of 14
    const int s2 = strip >> 2;
    const int ti = s2 % NROWP;                         // 28 row pairs
    const int b  = s2 / NROWP;

    const int oi0 = 2 * ti;
    const int oj0 = 14 * cj;
    const int xr0 = 4 * ti - 1;                        // first x row
    const int xc0 = 28 * cj - 1;                       // first x col

    const bool okTop     = (ti != 0);
    const bool okBot     = (ti != NROWP - 1);
    const bool leftSkip  = (cj == 0);
    const bool rightSkip = (cj == 3);

    const float2 NEG  = make_float2(-FLT_MAX, -FLT_MAX);
    const float2 ZERO = make_float2(0.f, 0.f);
    const float wv0 = 0.125f, wv1 = 0.375f;            // (1,3,3,1)/8

    const float2* base = x + (size_t)b * 112 * ROWSTR + chHalf * 32 + lane;

    // Clamped row offsets (float2 units), warp-uniform. Row -1 (top) and
    // rows 112/113 (bottom) clamp; their values only ever reach zeroed /
    // NEG-substituted lanes.
    int rowOff[7];
#pragma unroll
    for (int k = 0; k < 7; k++) {
        int gr = xr0 + k;
        gr = gr < 0 ? 0 : (gr > 111 ? 111 : gr);
        rowOff[k] = gr * ROWSTR;
    }

    float2* ob = out + ((size_t)(b * 56 + oi0) * 56 + oj0) * 64
                     + chHalf * 32 + lane;

    // Prime: column xc0 -> cmPrev
    float2 cmPrev[6];
    {
        float2 xv[7];
        LOADCOL(xv, 0);
        MAKECM(cmPrev, xv);
    }

    float2 acc[2][2];                                  // [row][col&1] ring
    acc[0][0]=ZERO; acc[0][1]=ZERO; acc[1][0]=ZERO; acc[1][1]=ZERO;

    // Double-buffered column pairs; buffer i&1 holds iteration i's pair.
    float2 xa[2][7], xb2[2][7];
    LOADCOL(xa[0],  1);
    LOADCOL(xb2[0], 2);

#pragma unroll
    for (int i = 0; i < 15; i++) {
        const int cur = i & 1, nxt = cur ^ 1;
        if (i < 14) {                                  // 14-load burst, iter i+1
            LOADCOL(xa[nxt],  3 + 2*i);
            LOADCOL(xb2[nxt], 4 + 2*i);
        }

        float2 cmA[6], cmB[6];
        MAKECM(cmA, xa[cur]);
        MAKECM(cmB, xb2[cur]);

        // Right edge: iteration 14's first column is x col 112 -> -inf pad.
        if (i == 14 && rightSkip) {
#pragma unroll
            for (int k = 0; k < 6; k++) cmA[k] = NEG;
        }

        STEP(cmPrev, cmA, 2*i);                        // y col ty = 2i
        STEP(cmA,    cmB, 2*i + 1);                    // y col ty = 2i+1

        if (i >= 1) {                                  // out col i-1 complete
            const int wl = i - 1, s = wl & 1;
#pragma unroll
            for (int rl = 0; rl < 2; rl++) {
                __stcs(&ob[((size_t)rl * 56 + wl) * 64], acc[rl][s]);
                acc[rl][s] = ZERO;
            }
        }

#pragma unroll
        for (int k = 0; k < 6; k++) cmPrev[k] = cmB[k];
    }
}

extern "C" void kernel_launch(void* const* d_in, const int* in_sizes, int n_in,
                              void* d_out, int out_size) {
    const float2* x = (const float2*)d_in[0];   // (32,112,112,128) f32
    // d_in[1] = blur kernel, baked into (1,3,3,1)/8
    float2* out = (float2*)d_out;               // (32,56,56,128) f32

    // 3584 strips x 2 channel halves = 7168 warp tasks, 4 warps/CTA
    dim3 block(32, 4);
    dim3 grid(7168 / 4);                        // 1792 blocks
    mbp_kernel<<<grid, block>>>(x, out);
}

// round 9
// speedup vs baseline: 1.0702x; 1.0702x over previous
#include <cuda_runtime.h>
#include <float.h>

// Fused MaxPool(2x2,s1,SAME) -> depthwise 3x3 binomial blur -> AvgPool(2x2,s2)
// == separable 4x4 stencil w=(1,3,3,1)/8 stride 2 over maxpool output y.
//
// R9: R3's exact pipeline (double-buffered column pairs, 14-load 256B bursts,
// predicated-select boundaries, 128-reg budget) with WCHUNK 14 -> 7 to double
// task count (14336) -> 6.05 waves: finer wave quantization, smaller tail.

#define WCHUNK 7                 // output cols per strip
#define NCH    8                 // 56 / WCHUNK
#define NROWP  28                // 56 / 2 output row-pairs
#define NXROWS 7                 // x rows per strip
#define NY     6                 // y rows per strip
#define NITER  (WCHUNK + 1)      // 8 pair iterations

__device__ __forceinline__ float2 f2max(float2 a, float2 b) {
    return make_float2(fmaxf(a.x,b.x), fmaxf(a.y,b.y));
}
__device__ __forceinline__ void f2fma(float2& a, float w, float2 v) {
    a.x = fmaf(w, v.x, a.x); a.y = fmaf(w, v.y, a.y);
}

#define ROWSTR (112*64)     // float2 per x row
#define PXSTR  64           // float2 per pixel

// Load 7 x-rows of one column (predicated selects, R3-style). Rows 1..4 are
// always in range; row 0 only invalid for the top strip, rows 5,6 only for
// the bottom strip.
#define LOADCOL(dst, c, cOk) do {                                         \
    const float2* _p = base + (long long)(c) * PXSTR;                     \
    dst[0] = ((cOk) && okTop) ? __ldg(_p)              : NEG;             \
    dst[1] = (cOk) ? __ldg(_p + 1*ROWSTR) : NEG;                          \
    dst[2] = (cOk) ? __ldg(_p + 2*ROWSTR) : NEG;                          \
    dst[3] = (cOk) ? __ldg(_p + 3*ROWSTR) : NEG;                          \
    dst[4] = (cOk) ? __ldg(_p + 4*ROWSTR) : NEG;                          \
    dst[5] = ((cOk) && okBot) ? __ldg(_p + 5*ROWSTR) : NEG;               \
    dst[6] = ((cOk) && okBot) ? __ldg(_p + 6*ROWSTR) : NEG;               \
} while (0)

// Finalize one y column (TY literal after unroll): vertical (1,3,3,1)/8
// reduction then scatter into the two pending output-column accumulators.
#define STEP(prevcm, curcm, TY) do {                                      \
    const bool _skip = ((TY)==0 && leftSkip) ||                           \
                       ((TY)==2*WCHUNK+1 && rightSkip);                   \
    if (!_skip) {                                                         \
        float2 yc[NY];                                                    \
        _Pragma("unroll")                                                 \
        for (int _k = 0; _k < NY; _k++)                                   \
            yc[_k] = f2max(prevcm[_k], curcm[_k]);                        \
        if (!okTop) yc[0]    = ZERO;                                      \
        if (!okBot) yc[NY-1] = ZERO;                                      \
        const int   _m  = (TY) >> 1;                                      \
        const float _wA = ((TY) & 1) ? wv1 : wv0;                         \
        const float _wB = ((TY) & 1) ? wv0 : wv1;                         \
        _Pragma("unroll")                                                 \
        for (int _rl = 0; _rl < 2; _rl++) {                               \
            float2 V = ZERO;                                              \
            f2fma(V, wv0, yc[2*_rl + 0]);                                 \
            f2fma(V, wv1, yc[2*_rl + 1]);                                 \
            f2fma(V, wv1, yc[2*_rl + 2]);                                 \
            f2fma(V, wv0, yc[2*_rl + 3]);                                 \
            if (_m < WCHUNK) f2fma(acc[_rl][_m & 1], _wA, V);             \
            if (_m >= 1)     f2fma(acc[_rl][(_m & 1) ^ 1], _wB, V);       \
        }                                                                 \
    }                                                                     \
} while (0)

__global__ void __launch_bounds__(128, 4)
mbp_kernel(const float2* __restrict__ x, float2* __restrict__ out) {
    const int lane   = threadIdx.x;
    const int wid    = blockIdx.x * 4 + threadIdx.y;   // 14336 warp tasks
    const int chHalf = wid & 1;
    const int strip  = wid >> 1;                       // 7168 strips
    const int cj = strip & (NCH - 1);                  // 8 col chunks of 7
    const int s2 = strip >> 3;
    const int ti = s2 % NROWP;                         // 28 row pairs
    const int b  = s2 / NROWP;

    const int oi0 = 2 * ti;
    const int oj0 = WCHUNK * cj;
    const int xr0 = 4 * ti - 1;
    const int xc0 = 2 * oj0 - 1;

    const float2 NEG  = make_float2(-FLT_MAX, -FLT_MAX);
    const float2 ZERO = make_float2(0.f, 0.f);
    const float wv0 = 0.125f, wv1 = 0.375f;            // (1,3,3,1)/8

    const bool okTop     = (ti != 0);
    const bool okBot     = (ti != NROWP - 1);
    const bool leftSkip  = (cj == 0);
    const bool rightSkip = (cj == NCH - 1);

    const float2* base = x + (size_t)b * 112 * 112 * 64 + chHalf * 32 + lane
                           + (long long)xr0 * ROWSTR;

    // Prime column xc0 -> cmPrev (column pair-maxes over x rows k,k+1)
    float2 cmPrev[NY];
    {
        float2 xv[NXROWS];
        LOADCOL(xv, xc0, !leftSkip);                   // xc0 < 0 only if cj==0
#pragma unroll
        for (int k = 0; k < NY; k++) cmPrev[k] = f2max(xv[k], xv[k+1]);
    }

    float2 acc[2][2];                                  // [row][col&1] ring
    acc[0][0]=ZERO; acc[0][1]=ZERO; acc[1][0]=ZERO; acc[1][1]=ZERO;

    float2* ob = out + ((size_t)(b * 56 + oi0) * 56 + oj0) * 64
                     + chHalf * 32 + lane;

    // Double-buffered column pairs: buffer i&1 holds cols of iteration i.
    float2 xa[2][NXROWS], xb2[2][NXROWS];
    LOADCOL(xa[0],  xc0 + 1, true);
    LOADCOL(xb2[0], xc0 + 2, true);

#pragma unroll
    for (int i = 0; i < NITER; i++) {
        const int cur = i & 1, nxt = cur ^ 1;
        if (i < NITER - 1) {                           // 14-load burst, iter i+1
            // Only the LAST prefetch (cols 112/113) can run off the right edge.
            const bool ok = (i < NITER - 2) || !rightSkip;
            LOADCOL(xa[nxt],  xc0 + 3 + 2*i, ok);
            LOADCOL(xb2[nxt], xc0 + 4 + 2*i, ok);
        }

        float2 cmA[NY], cmB[NY];
#pragma unroll
        for (int k = 0; k < NY; k++) {
            cmA[k] = f2max(xa[cur][k],  xa[cur][k+1]);
            cmB[k] = f2max(xb2[cur][k], xb2[cur][k+1]);
        }

        STEP(cmPrev, cmA, 2*i);                        // y col ty = 2i
        STEP(cmA,    cmB, 2*i + 1);                    // y col ty = 2i+1

        if (i >= 1) {                                  // out col i-1 complete
            const int wl = i - 1, s = wl & 1;
#pragma unroll
            for (int rl = 0; rl < 2; rl++) {
                ob[((size_t)rl * 56 + wl) * 64] = acc[rl][s];
                acc[rl][s] = ZERO;
            }
        }

#pragma unroll
        for (int k = 0; k < NY; k++) cmPrev[k] = cmB[k];
    }
}

extern "C" void kernel_launch(void* const* d_in, const int* in_sizes, int n_in,
                              void* d_out, int out_size) {
    const float2* x = (const float2*)d_in[0];   // (32,112,112,128) f32
    // d_in[1] = blur kernel, baked into (1,3,3,1)/8
    float2* out = (float2*)d_out;               // (32,56,56,128) f32

    // 7168 strips x 2 channel halves = 14336 warp tasks, 4 warps/CTA
    dim3 block(32, 4);
    dim3 grid(14336 / 4);                       // 3584 blocks
    mbp_kernel<<<grid, block>>>(x, out);
}

// round 10
// speedup vs baseline: 1.0993x; 1.0272x over previous
#include <cuda_runtime.h>
#include <float.h>

// Fused MaxPool(2x2,s1,SAME) -> depthwise 3x3 binomial blur -> AvgPool(2x2,s2)
// == separable 4x4 stencil w=(1,3,3,1)/8 stride 2 over maxpool output y.
//
// R10: R3's kernel body verbatim (the proven 39.5us codegen: double-buffered
// column pairs, 14-load 256B bursts, full compute block between burst and
// consume). Only scheduling-level changes:
//   - 64-thread CTAs (8 CTAs/SM at the same 16 warps/SM): finer allocation
//     and drain granularity for the CTA scheduler.
//   - __stcs output stores: dead output lines don't evict the input lines
//     L2 still needs for the 1.75x vertical-overlap dedupe.

#define NROWP  28
#define ROWSTR (112*64)     // float2 per x row
#define PXSTR  64           // float2 per pixel

__device__ __forceinline__ float2 f2max(float2 a, float2 b) {
    return make_float2(fmaxf(a.x,b.x), fmaxf(a.y,b.y));
}
__device__ __forceinline__ void f2fma(float2& a, float w, float2 v) {
    a.x = fmaf(w, v.x, a.x); a.y = fmaf(w, v.y, a.y);
}

// Load 7 x-rows of one column. Rows 1..4 are always in range; row 0 only
// invalid for the top strip, rows 5,6 only for the bottom strip.
#define LOADCOL(dst, c, cOk) do {                                         \
    const float2* _p = base + (long long)(c) * PXSTR;                     \
    dst[0] = ((cOk) && okTop) ? __ldg(_p)              : NEG;             \
    dst[1] = (cOk) ? __ldg(_p + 1*ROWSTR) : NEG;                          \
    dst[2] = (cOk) ? __ldg(_p + 2*ROWSTR) : NEG;                          \
    dst[3] = (cOk) ? __ldg(_p + 3*ROWSTR) : NEG;                          \
    dst[4] = (cOk) ? __ldg(_p + 4*ROWSTR) : NEG;                          \
    dst[5] = ((cOk) && okBot) ? __ldg(_p + 5*ROWSTR) : NEG;               \
    dst[6] = ((cOk) && okBot) ? __ldg(_p + 6*ROWSTR) : NEG;               \
} while (0)

// Finalize one y column (TY literal after unroll): vertical (1,3,3,1)/8
// reduction then scatter into the two pending output-column accumulators.
#define STEP(prevcm, curcm, TY) do {                                      \
    const bool _skip = ((TY)==0 && leftSkip) || ((TY)==29 && rightSkip);  \
    if (!_skip) {                                                         \
        float2 yc[6];                                                     \
        _Pragma("unroll")                                                 \
        for (int _k = 0; _k < 6; _k++) yc[_k] = f2max(prevcm[_k], curcm[_k]); \
        if (!okTop) yc[0] = ZERO;                                         \
        if (!okBot) yc[5] = ZERO;                                         \
        const int   _m  = (TY) >> 1;                                      \
        const float _wA = ((TY) & 1) ? wv1 : wv0;                         \
        const float _wB = ((TY) & 1) ? wv0 : wv1;                         \
        _Pragma("unroll")                                                 \
        for (int _rl = 0; _rl < 2; _rl++) {                               \
            float2 V = ZERO;                                              \
            f2fma(V, wv0, yc[2*_rl + 0]);                                 \
            f2fma(V, wv1, yc[2*_rl + 1]);                                 \
            f2fma(V, wv1, yc[2*_rl + 2]);                                 \
            f2fma(V, wv0, yc[2*_rl + 3]);                                 \
            if (_m < 14) f2fma(acc[_rl][_m & 1], _wA, V);                 \
            if (_m >= 1) f2fma(acc[_rl][(_m & 1) ^ 1], _wB, V);           \
        }                                                                 \
    }                                                                     \
} while (0)

__global__ void __launch_bounds__(64, 8)
mbp_kernel(const float2* __restrict__ x, float2* __restrict__ out) {
    const int lane   = threadIdx.x;
    const int wid    = blockIdx.x * 2 + threadIdx.y;   // 7168 warp tasks
    const int chHalf = wid & 1;
    const int strip  = wid >> 1;                       // 3584 strips
    const int cj = strip & 3;                          // 4 col chunks of 14
    const int s2 = strip >> 2;
    const int ti = s2 % NROWP;                         // 28 row pairs
    const int b  = s2 / NROWP;

    const int oi0 = 2 * ti;
    const int oj0 = 14 * cj;
    const int xr0 = 4 * ti - 1;
    const int xc0 = 28 * cj - 1;

    const float2 NEG  = make_float2(-FLT_MAX, -FLT_MAX);
    const float2 ZERO = make_float2(0.f, 0.f);
    const float wv0 = 0.125f, wv1 = 0.375f;            // (1,3,3,1)/8

    const bool okTop     = (ti != 0);
    const bool okBot     = (ti != NROWP - 1);
    const bool leftSkip  = (cj == 0);
    const bool rightSkip = (cj == 3);

    const float2* base = x + (size_t)b * 112 * 112 * 64 + chHalf * 32 + lane
                           + (long long)xr0 * ROWSTR;

    // Prime column xc0 -> cmPrev (column pair-maxes over x rows k,k+1)
    float2 cmPrev[6];
    {
        float2 xv[7];
        LOADCOL(xv, xc0, !leftSkip);                   // xc0 < 0 only if cj==0
#pragma unroll
        for (int k = 0; k < 6; k++) cmPrev[k] = f2max(xv[k], xv[k+1]);
    }

    float2 acc[2][2];                                  // [row][col&1] ring
    acc[0][0]=ZERO; acc[0][1]=ZERO; acc[1][0]=ZERO; acc[1][1]=ZERO;

    float2* ob = out + ((size_t)(b * 56 + oi0) * 56 + oj0) * 64
                     + chHalf * 32 + lane;

    // Double-buffered column pairs: buffer i&1 holds cols of iteration i.
    float2 xa[2][7], xb2[2][7];
    LOADCOL(xa[0],  xc0 + 1, true);
    LOADCOL(xb2[0], xc0 + 2, true);

#pragma unroll
    for (int i = 0; i < 15; i++) {
        const int cur = i & 1, nxt = cur ^ 1;
        if (i < 14) {                                  // prefetch iter i+1
            const bool ok = (i < 13) || !rightSkip;    // only cols 112/113 bad
            LOADCOL(xa[nxt],  xc0 + 3 + 2*i, ok);
            LOADCOL(xb2[nxt], xc0 + 4 + 2*i, ok);
        }

        float2 cmA[6], cmB[6];
#pragma unroll
        for (int k = 0; k < 6; k++) {
            cmA[k] = f2max(xa[cur][k],  xa[cur][k+1]);
            cmB[k] = f2max(xb2[cur][k], xb2[cur][k+1]);
        }

        STEP(cmPrev, cmA, 2*i);                        // y col ty = 2i
        STEP(cmA,    cmB, 2*i + 1);                    // y col ty = 2i+1

        if (i >= 1) {                                  // out col i-1 done
            const int wl = i - 1, slot = wl & 1;
#pragma unroll
            for (int rl = 0; rl < 2; rl++) {
                __stcs(&ob[((size_t)rl * 56 + wl) * 64], acc[rl][slot]);
                acc[rl][slot] = ZERO;
            }
        }

#pragma unroll
        for (int k = 0; k < 6; k++) cmPrev[k] = cmB[k];
    }
}

extern "C" void kernel_launch(void* const* d_in, const int* in_sizes, int n_in,
                              void* d_out, int out_size) {
    const float2* x = (const float2*)d_in[0];   // (32,112,112,128) f32
    // d_in[1] = blur kernel, baked into (1,3,3,1)/8
    float2* out = (float2*)d_out;               // (32,56,56,128) f32

    // 3584 strips x 2 channel halves = 7168 warp tasks, 2 warps/CTA
    dim3 block(32, 2);
    dim3 grid(7168 / 2);                        // 3584 blocks
    mbp_kernel<<<grid, block>>>(x, out);
}